// round 6
// baseline (speedup 1.0000x reference)
#include <cuda_runtime.h>

// SelfAttn: B=16, C=64, H=W=64. theta/phi: 8 ch, g: 32 ch.
// phi,g maxpooled 2x2 -> M=1024 keys. HW=4096 queries.

#define BATCH 16
#define CDIM  64
#define HWDIM 4096
#define MDIM  1024
#define CT    8
#define CG    32

typedef unsigned long long u64;

__device__ __forceinline__ u64 pack2(float lo, float hi) {
    u64 r; asm("mov.b64 %0, {%1,%2};" : "=l"(r) : "f"(lo), "f"(hi)); return r;
}
__device__ __forceinline__ float2 unpack2(u64 v) {
    float2 r; asm("mov.b64 {%0,%1}, %2;" : "=f"(r.x), "=f"(r.y) : "l"(v)); return r;
}
__device__ __forceinline__ u64 ffma2(u64 a, u64 b, u64 c) {
    u64 d; asm("fma.rn.f32x2 %0, %1, %2, %3;" : "=l"(d) : "l"(a), "l"(b), "l"(c)); return d;
}
__device__ __forceinline__ u64 fmul2(u64 a, u64 b) {
    u64 d; asm("mul.rn.f32x2 %0, %1, %2;" : "=l"(d) : "l"(a), "l"(b)); return d;
}
__device__ __forceinline__ float ex2f(float x) {
    float r; asm("ex2.approx.ftz.f32 %0, %1;" : "=f"(r) : "f"(x)); return r;
}
__device__ __forceinline__ u64 max2(u64 a, u64 b) {
    float2 x = unpack2(a), y = unpack2(b);
    return pack2(fmaxf(x.x, y.x), fmaxf(x.y, y.y));
}

#define LOG2E 1.4426950408889634f

// Scratch (allocation-free rule: __device__ globals)
__device__ float d_theta[BATCH * HWDIM * CT];   // [b][n][8]
__device__ float d_phi  [BATCH * MDIM  * CT];   // [b][m][8]
__device__ float d_gbuf [BATCH * MDIM  * CG];   // [b][m][32]

// ---------------------------------------------------------------------------
// Kernel A: 1x1 projections + fused 2x2 maxpool for phi/g.
// One thread per PIXEL. CTA = 128 threads = 2 rows x 64 cols (one pool strip).
// grid (32, 16). Horizontal pool max: shfl_xor(1). Vertical: smem exchange.
// ---------------------------------------------------------------------------
__global__ __launch_bounds__(128) void proj_kernel(
    const float* __restrict__ x,
    const float* __restrict__ wt,
    const float* __restrict__ wp,
    const float* __restrict__ wg)
{
    __shared__ __align__(16) u64 s_wt2[CDIM * 4];
    __shared__ __align__(16) u64 s_wp2[CDIM * 4];
    __shared__ __align__(16) u64 s_wg2[CDIM * 16];
    __shared__ __align__(16) u64 s_pool[32][20];   // [pooled col][4 phi + 16 g]
    int tid = threadIdx.x;
    for (int i = tid; i < CDIM * 4; i += 128) {
        int c = i >> 2, j = i & 3;
        s_wt2[i] = pack2(wt[(2 * j) * CDIM + c], wt[(2 * j + 1) * CDIM + c]);
        s_wp2[i] = pack2(wp[(2 * j) * CDIM + c], wp[(2 * j + 1) * CDIM + c]);
    }
    for (int i = tid; i < CDIM * 16; i += 128) {
        int c = i >> 4, j = i & 15;
        s_wg2[i] = pack2(wg[(2 * j) * CDIM + c], wg[(2 * j + 1) * CDIM + c]);
    }
    __syncthreads();

    int b   = blockIdx.y;
    int py  = blockIdx.x;            // row-pair 0..31
    int row = 2 * py + (tid >> 6);
    int col = tid & 63;
    int pix = row * 64 + col;
    const float* xb = x + (size_t)b * CDIM * HWDIM;

    u64 th[4], ph[4], gg[16];
#pragma unroll
    for (int j = 0; j < 4; j++) { th[j] = 0ull; ph[j] = 0ull; }
#pragma unroll
    for (int j = 0; j < 16; j++) gg[j] = 0ull;

#pragma unroll 8
    for (int c = 0; c < CDIM; c++) {
        float a = xb[(size_t)c * HWDIM + pix];
        u64 x2 = pack2(a, a);
        const ulonglong2* wtp = (const ulonglong2*)(s_wt2 + c * 4);
        const ulonglong2* wpp = (const ulonglong2*)(s_wp2 + c * 4);
        const ulonglong2* wgp = (const ulonglong2*)(s_wg2 + c * 16);
#pragma unroll
        for (int jj = 0; jj < 2; jj++) {
            ulonglong2 w = wtp[jj];
            th[2 * jj]     = ffma2(w.x, x2, th[2 * jj]);
            th[2 * jj + 1] = ffma2(w.y, x2, th[2 * jj + 1]);
            ulonglong2 v = wpp[jj];
            ph[2 * jj]     = ffma2(v.x, x2, ph[2 * jj]);
            ph[2 * jj + 1] = ffma2(v.y, x2, ph[2 * jj + 1]);
        }
#pragma unroll
        for (int jj = 0; jj < 8; jj++) {
            ulonglong2 w = wgp[jj];
            gg[2 * jj]     = ffma2(w.x, x2, gg[2 * jj]);
            gg[2 * jj + 1] = ffma2(w.y, x2, gg[2 * jj + 1]);
        }
    }

    // theta store (2 x STG.128)
    {
        ulonglong2* tp = (ulonglong2*)&d_theta[((size_t)b * HWDIM + pix) * CT];
        tp[0] = make_ulonglong2(th[0], th[1]);
        tp[1] = make_ulonglong2(th[2], th[3]);
    }

    // horizontal pool max (adjacent lanes = adjacent cols)
#pragma unroll
    for (int j = 0; j < 4; j++)
        ph[j] = max2(ph[j], __shfl_xor_sync(0xffffffffu, ph[j], 1));
#pragma unroll
    for (int j = 0; j < 16; j++)
        gg[j] = max2(gg[j], __shfl_xor_sync(0xffffffffu, gg[j], 1));

    // vertical pool max via smem: odd-row threads publish, even-row combine
    bool evencol = !(col & 1);
    int pc = col >> 1;
    if (tid >= 64 && evencol) {
#pragma unroll
        for (int j = 0; j < 4; j++)  s_pool[pc][j]     = ph[j];
#pragma unroll
        for (int j = 0; j < 16; j++) s_pool[pc][4 + j] = gg[j];
    }
    __syncthreads();
    if (tid < 64 && evencol) {
        int pp = py * 32 + pc;
        u64* pph = (u64*)&d_phi[((size_t)b * MDIM + pp) * CT];
#pragma unroll
        for (int j = 0; j < 4; j++)  pph[j] = max2(ph[j], s_pool[pc][j]);
        u64* pg = (u64*)&d_gbuf[((size_t)b * MDIM + pp) * CG];
#pragma unroll
        for (int j = 0; j < 16; j++) pg[j] = max2(gg[j], s_pool[pc][4 + j]);
    }
}

// ---------------------------------------------------------------------------
// Kernel B: fully fused attention + softmax + w_o GEMV + residual.
// 512 threads, ONE query per thread -> 16 warps/SM (4/SMSP) for latency hiding.
// grid (8, 16) = 128 CTAs, 1 CTA/SM (smem 168KB), single wave.
// All inner-loop smem reads are warp-broadcast LDS.128.
// theta pre-scaled by log2e; ex2.approx; fixed shift cancels in normalization.
// ---------------------------------------------------------------------------
__global__ __launch_bounds__(512) void attn_kernel(
    const float* __restrict__ x,
    const float* __restrict__ wo,
    const float* __restrict__ gamma,
    float* __restrict__ out)
{
    extern __shared__ u64 smem[];
    u64* s_phi = smem;                    // [1024][4]  pairs of phi channels
    u64* s_g   = smem + MDIM * 4;         // [1024][16] pairs of g channels
    u64* s_wo2 = s_g + MDIM * 16;         // [64][16]   pairs over k

    int tid = threadIdx.x;
    int qt  = blockIdx.x;
    int b   = blockIdx.y;

    {   // cooperative smem fill (float4)
        const float4* sph = (const float4*)&d_phi[(size_t)b * MDIM * CT];
        float4* dph = (float4*)s_phi;
        for (int i = tid; i < MDIM * CT / 4; i += 512) dph[i] = sph[i];
        const float4* sg = (const float4*)&d_gbuf[(size_t)b * MDIM * CG];
        float4* dg = (float4*)s_g;
        for (int i = tid; i < MDIM * CG / 4; i += 512) dg[i] = sg[i];
        for (int i = tid; i < CDIM * 16; i += 512) {
            int c = i >> 4, j = i & 15;
            s_wo2[i] = pack2(wo[c * CG + 2 * j], wo[c * CG + 2 * j + 1]);
        }
    }
    __syncthreads();

    int n = qt * 512 + tid;
    u64 ta[4];
    {
        const float4* thp = (const float4*)&d_theta[((size_t)b * HWDIM + n) * CT];
        float4 t0 = thp[0], t1 = thp[1];
        ta[0] = pack2(t0.x * LOG2E, t0.y * LOG2E);
        ta[1] = pack2(t0.z * LOG2E, t0.w * LOG2E);
        ta[2] = pack2(t1.x * LOG2E, t1.y * LOG2E);
        ta[3] = pack2(t1.z * LOG2E, t1.w * LOG2E);
    }
    const u64 s_init = pack2(-12.0f * LOG2E, 0.0f);   // uniform shift, cancels

    float sum = 0.0f;
    u64 acc[16];
#pragma unroll
    for (int k = 0; k < 16; k++) acc[k] = 0ull;

#pragma unroll 2
    for (int m = 0; m < MDIM; m++) {
        const ulonglong2* pp = (const ulonglong2*)(s_phi + m * 4);
        ulonglong2 pa = pp[0], pb = pp[1];
        u64 s0 = ffma2(ta[0], pa.x, s_init);
        s0 = ffma2(ta[1], pa.y, s0);
        s0 = ffma2(ta[2], pb.x, s0);
        s0 = ffma2(ta[3], pb.y, s0);
        float2 v0 = unpack2(s0);
        float e = ex2f(v0.x + v0.y);
        sum += e;
        u64 e2 = pack2(e, e);
        const ulonglong2* gp = (const ulonglong2*)(s_g + m * 16);
#pragma unroll
        for (int q = 0; q < 8; q++) {
            ulonglong2 gv = gp[q];
            acc[2 * q]     = ffma2(e2, gv.x, acc[2 * q]);
            acc[2 * q + 1] = ffma2(e2, gv.y, acc[2 * q + 1]);
        }
    }

    // normalize
    {
        float inv = 1.0f / sum;
        u64 i2 = pack2(inv, inv);
#pragma unroll
        for (int j = 0; j < 16; j++) acc[j] = fmul2(acc[j], i2);
    }

    // epilogue: o = wo @ acc ; out = gamma*o + x
    float gm = *gamma;
    const float* xb = x   + (size_t)b * CDIM * HWDIM + n;
    float*       ob = out + (size_t)b * CDIM * HWDIM + n;
#pragma unroll 4
    for (int c = 0; c < CDIM; c++) {
        const ulonglong2* wr = (const ulonglong2*)(s_wo2 + c * 16);
        u64 v0 = 0ull;
#pragma unroll
        for (int j = 0; j < 8; j++) {
            ulonglong2 w = wr[j];
            v0 = ffma2(w.x, acc[2 * j],     v0);
            v0 = ffma2(w.y, acc[2 * j + 1], v0);
        }
        float2 a = unpack2(v0);
        ob[(size_t)c * HWDIM] = fmaf(gm, a.x + a.y, xb[(size_t)c * HWDIM]);
    }
}

// ---------------------------------------------------------------------------
extern "C" void kernel_launch(void* const* d_in, const int* in_sizes, int n_in,
                              void* d_out, int out_size)
{
    const float* x  = (const float*)d_in[0];
    const float* wt = (const float*)d_in[1];
    const float* wp = (const float*)d_in[2];
    const float* wg = (const float*)d_in[3];
    const float* wo = (const float*)d_in[4];
    const float* gm = (const float*)d_in[5];
    float* out = (float*)d_out;

    proj_kernel<<<dim3(32, BATCH), 128>>>(x, wt, wp, wg);

    int smem_bytes = (MDIM * 4 + MDIM * 16 + CDIM * 16) * (int)sizeof(u64); // 172032
    cudaFuncSetAttribute(attn_kernel, cudaFuncAttributeMaxDynamicSharedMemorySize,
                         smem_bytes);
    attn_kernel<<<dim3(HWDIM / 512, BATCH), 512, smem_bytes>>>(x, wo, gm, out);
}

// round 7
// speedup vs baseline: 1.3238x; 1.3238x over previous
#include <cuda_runtime.h>

// SelfAttn: B=16, C=64, H=W=64. theta/phi: 8 ch, g: 32 ch.
// phi,g maxpooled 2x2 -> M=1024 keys. HW=4096 queries.

#define BATCH 16
#define CDIM  64
#define HWDIM 4096
#define MDIM  1024
#define CT    8
#define CG    32
#define MSPLIT 2
#define MHALF (MDIM / MSPLIT)   // 512

typedef unsigned long long u64;

__device__ __forceinline__ u64 pack2(float lo, float hi) {
    u64 r; asm("mov.b64 %0, {%1,%2};" : "=l"(r) : "f"(lo), "f"(hi)); return r;
}
__device__ __forceinline__ float2 unpack2(u64 v) {
    float2 r; asm("mov.b64 {%0,%1}, %2;" : "=f"(r.x), "=f"(r.y) : "l"(v)); return r;
}
__device__ __forceinline__ u64 ffma2(u64 a, u64 b, u64 c) {
    u64 d; asm("fma.rn.f32x2 %0, %1, %2, %3;" : "=l"(d) : "l"(a), "l"(b), "l"(c)); return d;
}
__device__ __forceinline__ u64 fadd2(u64 a, u64 b) {
    u64 d; asm("add.rn.f32x2 %0, %1, %2;" : "=l"(d) : "l"(a), "l"(b)); return d;
}
__device__ __forceinline__ float ex2f(float x) {
    float r; asm("ex2.approx.ftz.f32 %0, %1;" : "=f"(r) : "f"(x)); return r;
}
__device__ __forceinline__ u64 max2(u64 a, u64 b) {
    float2 x = unpack2(a), y = unpack2(b);
    return pack2(fmaxf(x.x, y.x), fmaxf(x.y, y.y));
}

#define LOG2E 1.4426950408889634f

// Scratch (allocation-free rule: __device__ globals)
__device__ float d_theta[BATCH * HWDIM * CT];            // [b][n][8]
__device__ float d_phi  [BATCH * MDIM  * CT];            // [b][m][8]
__device__ float d_gbuf [BATCH * MDIM  * CG];            // [b][m][32]
__device__ float d_part [BATCH * MSPLIT * CG * HWDIM];   // [b][s][k][n]
__device__ float d_psum [BATCH * MSPLIT * HWDIM];        // [b][s][n]

// ---------------------------------------------------------------------------
// Kernel A: 1x1 projections + fused 2x2 maxpool for phi/g.
// One thread per PIXEL. CTA = 128 threads = 2 rows x 64 cols (one pool strip).
// grid (32, 16). Horizontal pool max: shfl_xor(1). Vertical: smem exchange.
// ---------------------------------------------------------------------------
__global__ __launch_bounds__(128) void proj_kernel(
    const float* __restrict__ x,
    const float* __restrict__ wt,
    const float* __restrict__ wp,
    const float* __restrict__ wg)
{
    __shared__ __align__(16) u64 s_wt2[CDIM * 4];
    __shared__ __align__(16) u64 s_wp2[CDIM * 4];
    __shared__ __align__(16) u64 s_wg2[CDIM * 16];
    __shared__ __align__(16) u64 s_pool[32][20];   // [pooled col][4 phi + 16 g]
    int tid = threadIdx.x;
    for (int i = tid; i < CDIM * 4; i += 128) {
        int c = i >> 2, j = i & 3;
        s_wt2[i] = pack2(wt[(2 * j) * CDIM + c], wt[(2 * j + 1) * CDIM + c]);
        s_wp2[i] = pack2(wp[(2 * j) * CDIM + c], wp[(2 * j + 1) * CDIM + c]);
    }
    for (int i = tid; i < CDIM * 16; i += 128) {
        int c = i >> 4, j = i & 15;
        s_wg2[i] = pack2(wg[(2 * j) * CDIM + c], wg[(2 * j + 1) * CDIM + c]);
    }
    __syncthreads();

    int b   = blockIdx.y;
    int py  = blockIdx.x;            // row-pair 0..31
    int row = 2 * py + (tid >> 6);
    int col = tid & 63;
    int pix = row * 64 + col;
    const float* xb = x + (size_t)b * CDIM * HWDIM;

    u64 th[4], ph[4], gg[16];
#pragma unroll
    for (int j = 0; j < 4; j++) { th[j] = 0ull; ph[j] = 0ull; }
#pragma unroll
    for (int j = 0; j < 16; j++) gg[j] = 0ull;

#pragma unroll 8
    for (int c = 0; c < CDIM; c++) {
        float a = xb[(size_t)c * HWDIM + pix];
        u64 x2 = pack2(a, a);
        const ulonglong2* wtp = (const ulonglong2*)(s_wt2 + c * 4);
        const ulonglong2* wpp = (const ulonglong2*)(s_wp2 + c * 4);
        const ulonglong2* wgp = (const ulonglong2*)(s_wg2 + c * 16);
#pragma unroll
        for (int jj = 0; jj < 2; jj++) {
            ulonglong2 w = wtp[jj];
            th[2 * jj]     = ffma2(w.x, x2, th[2 * jj]);
            th[2 * jj + 1] = ffma2(w.y, x2, th[2 * jj + 1]);
            ulonglong2 v = wpp[jj];
            ph[2 * jj]     = ffma2(v.x, x2, ph[2 * jj]);
            ph[2 * jj + 1] = ffma2(v.y, x2, ph[2 * jj + 1]);
        }
#pragma unroll
        for (int jj = 0; jj < 8; jj++) {
            ulonglong2 w = wgp[jj];
            gg[2 * jj]     = ffma2(w.x, x2, gg[2 * jj]);
            gg[2 * jj + 1] = ffma2(w.y, x2, gg[2 * jj + 1]);
        }
    }

    // theta store (2 x STG.128)
    {
        ulonglong2* tp = (ulonglong2*)&d_theta[((size_t)b * HWDIM + pix) * CT];
        tp[0] = make_ulonglong2(th[0], th[1]);
        tp[1] = make_ulonglong2(th[2], th[3]);
    }

    // horizontal pool max (adjacent lanes = adjacent cols)
#pragma unroll
    for (int j = 0; j < 4; j++)
        ph[j] = max2(ph[j], __shfl_xor_sync(0xffffffffu, ph[j], 1));
#pragma unroll
    for (int j = 0; j < 16; j++)
        gg[j] = max2(gg[j], __shfl_xor_sync(0xffffffffu, gg[j], 1));

    // vertical pool max via smem: odd-row threads publish, even-row combine
    bool evencol = !(col & 1);
    int pc = col >> 1;
    if (tid >= 64 && evencol) {
#pragma unroll
        for (int j = 0; j < 4; j++)  s_pool[pc][j]     = ph[j];
#pragma unroll
        for (int j = 0; j < 16; j++) s_pool[pc][4 + j] = gg[j];
    }
    __syncthreads();
    if (tid < 64 && evencol) {
        int pp = py * 32 + pc;
        u64* pph = (u64*)&d_phi[((size_t)b * MDIM + pp) * CT];
#pragma unroll
        for (int j = 0; j < 4; j++)  pph[j] = max2(ph[j], s_pool[pc][j]);
        u64* pg = (u64*)&d_gbuf[((size_t)b * MDIM + pp) * CG];
#pragma unroll
        for (int j = 0; j < 16; j++) pg[j] = max2(gg[j], s_pool[pc][4 + j]);
    }
}

// ---------------------------------------------------------------------------
// Kernel B: fused attention over half the keys, TWO queries per thread.
// grid (8 qtile, 2 split, 16 batch) = 256 CTAs, 256 threads, smem 80KB ->
// 2 CTAs/SM = 4 warps/SMSP. LDS amortized over 2 queries -> FMA-pipe-bound.
// theta pre-scaled by log2e; ex2.approx; fixed shift cancels at combine.
// ---------------------------------------------------------------------------
__global__ __launch_bounds__(256, 2) void attn_kernel(void)
{
    extern __shared__ u64 smem[];
    u64* s_phi = smem;                 // [512][4]  pairs of phi channels
    u64* s_g   = smem + MHALF * 4;     // [512][16] pairs of g channels

    int tid = threadIdx.x;
    int qt  = blockIdx.x;
    int sp  = blockIdx.y;
    int b   = blockIdx.z;
    int m0  = sp * MHALF;

    {   // cooperative smem fill (float4)
        const float4* sph = (const float4*)&d_phi[((size_t)b * MDIM + m0) * CT];
        float4* dph = (float4*)s_phi;
        for (int i = tid; i < MHALF * CT / 4; i += 256) dph[i] = sph[i];
        const float4* sg = (const float4*)&d_gbuf[((size_t)b * MDIM + m0) * CG];
        float4* dg = (float4*)s_g;
        for (int i = tid; i < MHALF * CG / 4; i += 256) dg[i] = sg[i];
    }
    __syncthreads();

    int n0 = qt * 512 + tid;
    int n1 = n0 + 256;
    u64 ta[4], tb[4];
    {
        const float4* thp = (const float4*)&d_theta[((size_t)b * HWDIM + n0) * CT];
        float4 t0 = thp[0], t1 = thp[1];
        ta[0] = pack2(t0.x * LOG2E, t0.y * LOG2E);
        ta[1] = pack2(t0.z * LOG2E, t0.w * LOG2E);
        ta[2] = pack2(t1.x * LOG2E, t1.y * LOG2E);
        ta[3] = pack2(t1.z * LOG2E, t1.w * LOG2E);
        const float4* thq = (const float4*)&d_theta[((size_t)b * HWDIM + n1) * CT];
        float4 u0 = thq[0], u1 = thq[1];
        tb[0] = pack2(u0.x * LOG2E, u0.y * LOG2E);
        tb[1] = pack2(u0.z * LOG2E, u0.w * LOG2E);
        tb[2] = pack2(u1.x * LOG2E, u1.y * LOG2E);
        tb[3] = pack2(u1.z * LOG2E, u1.w * LOG2E);
    }
    const u64 s_init = pack2(-12.0f * LOG2E, 0.0f);   // uniform shift, cancels

    u64 sum2 = 0ull;                      // (sum0, sum1)
    u64 acc0[16], acc1[16];
#pragma unroll
    for (int k = 0; k < 16; k++) { acc0[k] = 0ull; acc1[k] = 0ull; }

#pragma unroll 4
    for (int m = 0; m < MHALF; m++) {
        const ulonglong2* pp = (const ulonglong2*)(s_phi + m * 4);
        ulonglong2 pa = pp[0], pb = pp[1];
        u64 s0 = ffma2(ta[0], pa.x, s_init);
        s0 = ffma2(ta[1], pa.y, s0);
        s0 = ffma2(ta[2], pb.x, s0);
        s0 = ffma2(ta[3], pb.y, s0);
        u64 s1 = ffma2(tb[0], pa.x, s_init);
        s1 = ffma2(tb[1], pa.y, s1);
        s1 = ffma2(tb[2], pb.x, s1);
        s1 = ffma2(tb[3], pb.y, s1);
        float2 v0 = unpack2(s0);
        float2 v1 = unpack2(s1);
        float e0 = ex2f(v0.x + v0.y);
        float e1 = ex2f(v1.x + v1.y);
        sum2 = fadd2(sum2, pack2(e0, e1));
        u64 e02 = pack2(e0, e0);
        u64 e12 = pack2(e1, e1);
        const ulonglong2* gp = (const ulonglong2*)(s_g + m * 16);
#pragma unroll
        for (int q = 0; q < 8; q++) {
            ulonglong2 gv = gp[q];
            acc0[2 * q]     = ffma2(e02, gv.x, acc0[2 * q]);
            acc0[2 * q + 1] = ffma2(e02, gv.y, acc0[2 * q + 1]);
            acc1[2 * q]     = ffma2(e12, gv.x, acc1[2 * q]);
            acc1[2 * q + 1] = ffma2(e12, gv.y, acc1[2 * q + 1]);
        }
    }

    // write unnormalized partials, [b][s][k][n] for coalescing
    float* pbase = &d_part[(((size_t)b * MSPLIT + sp) * CG) * HWDIM];
#pragma unroll
    for (int j = 0; j < 16; j++) {
        float2 a = unpack2(acc0[j]);
        pbase[(size_t)(2 * j) * HWDIM + n0]     = a.x;
        pbase[(size_t)(2 * j + 1) * HWDIM + n0] = a.y;
        float2 c = unpack2(acc1[j]);
        pbase[(size_t)(2 * j) * HWDIM + n1]     = c.x;
        pbase[(size_t)(2 * j + 1) * HWDIM + n1] = c.y;
    }
    float2 s = unpack2(sum2);
    d_psum[((size_t)b * MSPLIT + sp) * HWDIM + n0] = s.x;
    d_psum[((size_t)b * MSPLIT + sp) * HWDIM + n1] = s.y;
}

// ---------------------------------------------------------------------------
// Kernel C: combine partials, normalize, w_o GEMV, gamma * o + x.
// grid (16, 16), 256 threads. One thread per query. Memory-bound (~64MB).
// ---------------------------------------------------------------------------
__global__ __launch_bounds__(256) void combine_kernel(
    const float* __restrict__ x,
    const float* __restrict__ wo,
    const float* __restrict__ gamma,
    float* __restrict__ out)
{
    __shared__ u64 s_wo2[CDIM * 16];   // pairs over k: {wo[c][2j], wo[c][2j+1]}
    int tid = threadIdx.x;
    for (int i = tid; i < CDIM * 16; i += 256) {
        int c = i >> 4, j = i & 15;
        s_wo2[i] = pack2(wo[c * CG + 2 * j], wo[c * CG + 2 * j + 1]);
    }
    __syncthreads();

    int b = blockIdx.y;
    int n = blockIdx.x * 256 + tid;

    const float* p0 = &d_part[(((size_t)b * MSPLIT + 0) * CG) * HWDIM + n];
    const float* p1 = &d_part[(((size_t)b * MSPLIT + 1) * CG) * HWDIM + n];
    float s0 = d_psum[((size_t)b * MSPLIT + 0) * HWDIM + n];
    float s1 = d_psum[((size_t)b * MSPLIT + 1) * HWDIM + n];
    float inv = 1.0f / (s0 + s1);

    u64 o2[16];
#pragma unroll
    for (int j = 0; j < 16; j++) {
        float a0 = (p0[(size_t)(2 * j) * HWDIM]     + p1[(size_t)(2 * j) * HWDIM])     * inv;
        float a1 = (p0[(size_t)(2 * j + 1) * HWDIM] + p1[(size_t)(2 * j + 1) * HWDIM]) * inv;
        o2[j] = pack2(a0, a1);
    }

    float gm = *gamma;
    const float* xb = x   + (size_t)b * CDIM * HWDIM + n;
    float*       ob = out + (size_t)b * CDIM * HWDIM + n;
#pragma unroll
    for (int c = 0; c < CDIM; c++) {
        u64 v2 = 0ull;
#pragma unroll
        for (int j = 0; j < 16; j++) v2 = ffma2(s_wo2[c * 16 + j], o2[j], v2);
        float2 v = unpack2(v2);
        ob[(size_t)c * HWDIM] = fmaf(gm, v.x + v.y, xb[(size_t)c * HWDIM]);
    }
}

// ---------------------------------------------------------------------------
extern "C" void kernel_launch(void* const* d_in, const int* in_sizes, int n_in,
                              void* d_out, int out_size)
{
    const float* x  = (const float*)d_in[0];
    const float* wt = (const float*)d_in[1];
    const float* wp = (const float*)d_in[2];
    const float* wg = (const float*)d_in[3];
    const float* wo = (const float*)d_in[4];
    const float* gm = (const float*)d_in[5];
    float* out = (float*)d_out;

    proj_kernel<<<dim3(32, BATCH), 128>>>(x, wt, wp, wg);

    int smem_bytes = (MHALF * 4 + MHALF * 16) * (int)sizeof(u64);   // 81920
    cudaFuncSetAttribute(attn_kernel, cudaFuncAttributeMaxDynamicSharedMemorySize,
                         smem_bytes);
    attn_kernel<<<dim3(HWDIM / 512, MSPLIT, BATCH), 256, smem_bytes>>>();

    combine_kernel<<<dim3(HWDIM / 256, BATCH), 256>>>(x, wo, gm, out);
}

// round 8
// speedup vs baseline: 1.3249x; 1.0008x over previous
#include <cuda_runtime.h>

// SelfAttn: B=16, C=64, H=W=64. theta/phi: 8 ch, g: 32 ch.
// phi,g maxpooled 2x2 -> M=1024 keys. HW=4096 queries.

#define BATCH 16
#define CDIM  64
#define HWDIM 4096
#define MDIM  1024
#define CT    8
#define CG    32
#define MSPLIT 2
#define MHALF (MDIM / MSPLIT)   // 512

typedef unsigned long long u64;

__device__ __forceinline__ u64 pack2(float lo, float hi) {
    u64 r; asm("mov.b64 %0, {%1,%2};" : "=l"(r) : "f"(lo), "f"(hi)); return r;
}
__device__ __forceinline__ float2 unpack2(u64 v) {
    float2 r; asm("mov.b64 {%0,%1}, %2;" : "=f"(r.x), "=f"(r.y) : "l"(v)); return r;
}
__device__ __forceinline__ u64 ffma2(u64 a, u64 b, u64 c) {
    u64 d; asm("fma.rn.f32x2 %0, %1, %2, %3;" : "=l"(d) : "l"(a), "l"(b), "l"(c)); return d;
}
__device__ __forceinline__ float ex2f(float x) {
    float r; asm("ex2.approx.ftz.f32 %0, %1;" : "=f"(r) : "f"(x)); return r;
}
__device__ __forceinline__ u64 max2(u64 a, u64 b) {
    float2 x = unpack2(a), y = unpack2(b);
    return pack2(fmaxf(x.x, y.x), fmaxf(x.y, y.y));
}

#define LOG2E 1.4426950408889634f

// Scratch (allocation-free rule: __device__ globals)
__device__ float d_theta[BATCH * HWDIM * CT];            // [b][n][8]
__device__ float d_phi  [BATCH * MDIM  * CT];            // [b][m][8]
__device__ float d_gbuf [BATCH * MDIM  * CG];            // [b][m][32]
__device__ float d_part [BATCH * MSPLIT * CG * HWDIM];   // [b][s][k][n]
__device__ float d_psum [BATCH * MSPLIT * HWDIM];        // [b][s][n]

// ---------------------------------------------------------------------------
// Kernel A: 1x1 projections + fused 2x2 maxpool for phi/g.
// One thread per PIXEL. CTA = 128 threads = 2 contiguous rows (one pool strip).
// x tile [64ch][128px] = 32KB staged via coalesced float4 burst into smem ->
// compute phase is pure issue/FMA-bound (LDS.32 feed, conflict-free).
// grid (32, 16). Horizontal pool max: shfl_xor(1). Vertical: smem exchange.
// ---------------------------------------------------------------------------
__global__ __launch_bounds__(128) void proj_kernel(
    const float* __restrict__ x,
    const float* __restrict__ wt,
    const float* __restrict__ wp,
    const float* __restrict__ wg)
{
    __shared__ __align__(16) u64 s_wt2[CDIM * 4];
    __shared__ __align__(16) u64 s_wp2[CDIM * 4];
    __shared__ __align__(16) u64 s_wg2[CDIM * 16];
    __shared__ __align__(16) float s_x[CDIM][128];
    __shared__ __align__(16) u64 s_pool[32][20];   // [pooled col][4 phi + 16 g]
    int tid = threadIdx.x;
    int b   = blockIdx.y;
    int py  = blockIdx.x;            // row-pair 0..31
    int pix0 = py * 128;             // CTA's pixels are contiguous [pix0, pix0+128)
    const float* xb = x + (size_t)b * CDIM * HWDIM;

    // stage x tile: 2048 float4, fully coalesced, 16 per thread (MLP burst)
#pragma unroll
    for (int i = 0; i < 16; i++) {
        int idx = i * 128 + tid;           // 0..2047
        int c = idx >> 5, j = idx & 31;
        ((float4*)s_x[c])[j] =
            ((const float4*)(xb + (size_t)c * HWDIM + pix0))[j];
    }
    // weights (packed channel pairs)
    for (int i = tid; i < CDIM * 4; i += 128) {
        int c = i >> 2, j = i & 3;
        s_wt2[i] = pack2(wt[(2 * j) * CDIM + c], wt[(2 * j + 1) * CDIM + c]);
        s_wp2[i] = pack2(wp[(2 * j) * CDIM + c], wp[(2 * j + 1) * CDIM + c]);
    }
    for (int i = tid; i < CDIM * 16; i += 128) {
        int c = i >> 4, j = i & 15;
        s_wg2[i] = pack2(wg[(2 * j) * CDIM + c], wg[(2 * j + 1) * CDIM + c]);
    }
    __syncthreads();

    int pix = pix0 + tid;
    int col = tid & 63;

    u64 th[4], ph[4], gg[16];
#pragma unroll
    for (int j = 0; j < 4; j++) { th[j] = 0ull; ph[j] = 0ull; }
#pragma unroll
    for (int j = 0; j < 16; j++) gg[j] = 0ull;

#pragma unroll 8
    for (int c = 0; c < CDIM; c++) {
        float a = s_x[c][tid];
        u64 x2 = pack2(a, a);
        const ulonglong2* wtp = (const ulonglong2*)(s_wt2 + c * 4);
        const ulonglong2* wpp = (const ulonglong2*)(s_wp2 + c * 4);
        const ulonglong2* wgp = (const ulonglong2*)(s_wg2 + c * 16);
#pragma unroll
        for (int jj = 0; jj < 2; jj++) {
            ulonglong2 w = wtp[jj];
            th[2 * jj]     = ffma2(w.x, x2, th[2 * jj]);
            th[2 * jj + 1] = ffma2(w.y, x2, th[2 * jj + 1]);
            ulonglong2 v = wpp[jj];
            ph[2 * jj]     = ffma2(v.x, x2, ph[2 * jj]);
            ph[2 * jj + 1] = ffma2(v.y, x2, ph[2 * jj + 1]);
        }
#pragma unroll
        for (int jj = 0; jj < 8; jj++) {
            ulonglong2 w = wgp[jj];
            gg[2 * jj]     = ffma2(w.x, x2, gg[2 * jj]);
            gg[2 * jj + 1] = ffma2(w.y, x2, gg[2 * jj + 1]);
        }
    }

    // theta store (2 x STG.128)
    {
        ulonglong2* tp = (ulonglong2*)&d_theta[((size_t)b * HWDIM + pix) * CT];
        tp[0] = make_ulonglong2(th[0], th[1]);
        tp[1] = make_ulonglong2(th[2], th[3]);
    }

    // horizontal pool max (adjacent lanes = adjacent cols)
#pragma unroll
    for (int j = 0; j < 4; j++)
        ph[j] = max2(ph[j], __shfl_xor_sync(0xffffffffu, ph[j], 1));
#pragma unroll
    for (int j = 0; j < 16; j++)
        gg[j] = max2(gg[j], __shfl_xor_sync(0xffffffffu, gg[j], 1));

    // vertical pool max via smem: second-row threads publish, first-row combine
    bool evencol = !(col & 1);
    int pc = col >> 1;
    if (tid >= 64 && evencol) {
#pragma unroll
        for (int j = 0; j < 4; j++)  s_pool[pc][j]     = ph[j];
#pragma unroll
        for (int j = 0; j < 16; j++) s_pool[pc][4 + j] = gg[j];
    }
    __syncthreads();
    if (tid < 64 && evencol) {
        int pp = py * 32 + pc;
        u64* pph = (u64*)&d_phi[((size_t)b * MDIM + pp) * CT];
#pragma unroll
        for (int j = 0; j < 4; j++)  pph[j] = max2(ph[j], s_pool[pc][j]);
        u64* pg = (u64*)&d_gbuf[((size_t)b * MDIM + pp) * CG];
#pragma unroll
        for (int j = 0; j < 16; j++) pg[j] = max2(gg[j], s_pool[pc][4 + j]);
    }
}

// ---------------------------------------------------------------------------
// Kernel B: fused attention over half the keys, TWO queries per thread.
// grid (8 qtile, 2 split, 16 batch) = 256 CTAs, 256 threads, smem 80KB ->
// 2 CTAs/SM = 4 warps/SMSP. LDS amortized over 2 queries -> FMA-pipe-bound.
// theta pre-scaled by log2e; ex2.approx; fixed shift cancels at combine.
// ---------------------------------------------------------------------------
__global__ __launch_bounds__(256, 2) void attn_kernel(void)
{
    extern __shared__ u64 smem[];
    u64* s_phi = smem;                 // [512][4]  pairs of phi channels
    u64* s_g   = smem + MHALF * 4;     // [512][16] pairs of g channels

    int tid = threadIdx.x;
    int qt  = blockIdx.x;
    int sp  = blockIdx.y;
    int b   = blockIdx.z;
    int m0  = sp * MHALF;

    {   // cooperative smem fill (float4)
        const float4* sph = (const float4*)&d_phi[((size_t)b * MDIM + m0) * CT];
        float4* dph = (float4*)s_phi;
        for (int i = tid; i < MHALF * CT / 4; i += 256) dph[i] = sph[i];
        const float4* sg = (const float4*)&d_gbuf[((size_t)b * MDIM + m0) * CG];
        float4* dg = (float4*)s_g;
        for (int i = tid; i < MHALF * CG / 4; i += 256) dg[i] = sg[i];
    }
    __syncthreads();

    int n0 = qt * 512 + tid;
    int n1 = n0 + 256;
    u64 ta[4], tb[4];
    {
        const float4* thp = (const float4*)&d_theta[((size_t)b * HWDIM + n0) * CT];
        float4 t0 = thp[0], t1 = thp[1];
        ta[0] = pack2(t0.x * LOG2E, t0.y * LOG2E);
        ta[1] = pack2(t0.z * LOG2E, t0.w * LOG2E);
        ta[2] = pack2(t1.x * LOG2E, t1.y * LOG2E);
        ta[3] = pack2(t1.z * LOG2E, t1.w * LOG2E);
        const float4* thq = (const float4*)&d_theta[((size_t)b * HWDIM + n1) * CT];
        float4 u0 = thq[0], u1 = thq[1];
        tb[0] = pack2(u0.x * LOG2E, u0.y * LOG2E);
        tb[1] = pack2(u0.z * LOG2E, u0.w * LOG2E);
        tb[2] = pack2(u1.x * LOG2E, u1.y * LOG2E);
        tb[3] = pack2(u1.z * LOG2E, u1.w * LOG2E);
    }
    const u64 s_init = pack2(-12.0f * LOG2E, 0.0f);   // uniform shift, cancels

    float sum0 = 0.0f, sum1 = 0.0f;
    u64 acc0[16], acc1[16];
#pragma unroll
    for (int k = 0; k < 16; k++) { acc0[k] = 0ull; acc1[k] = 0ull; }

#pragma unroll 8
    for (int m = 0; m < MHALF; m++) {
        const ulonglong2* pp = (const ulonglong2*)(s_phi + m * 4);
        ulonglong2 pa = pp[0], pb = pp[1];
        u64 s0 = ffma2(ta[0], pa.x, s_init);
        s0 = ffma2(ta[1], pa.y, s0);
        s0 = ffma2(ta[2], pb.x, s0);
        s0 = ffma2(ta[3], pb.y, s0);
        u64 s1 = ffma2(tb[0], pa.x, s_init);
        s1 = ffma2(tb[1], pa.y, s1);
        s1 = ffma2(tb[2], pb.x, s1);
        s1 = ffma2(tb[3], pb.y, s1);
        float2 v0 = unpack2(s0);
        float2 v1 = unpack2(s1);
        float e0 = ex2f(v0.x + v0.y);
        float e1 = ex2f(v1.x + v1.y);
        sum0 += e0;
        sum1 += e1;
        u64 e02 = pack2(e0, e0);
        u64 e12 = pack2(e1, e1);
        const ulonglong2* gp = (const ulonglong2*)(s_g + m * 16);
#pragma unroll
        for (int q = 0; q < 8; q++) {
            ulonglong2 gv = gp[q];
            acc0[2 * q]     = ffma2(e02, gv.x, acc0[2 * q]);
            acc0[2 * q + 1] = ffma2(e02, gv.y, acc0[2 * q + 1]);
            acc1[2 * q]     = ffma2(e12, gv.x, acc1[2 * q]);
            acc1[2 * q + 1] = ffma2(e12, gv.y, acc1[2 * q + 1]);
        }
    }

    // write unnormalized partials, [b][s][k][n] for coalescing
    float* pbase = &d_part[(((size_t)b * MSPLIT + sp) * CG) * HWDIM];
#pragma unroll
    for (int j = 0; j < 16; j++) {
        float2 a = unpack2(acc0[j]);
        pbase[(size_t)(2 * j) * HWDIM + n0]     = a.x;
        pbase[(size_t)(2 * j + 1) * HWDIM + n0] = a.y;
        float2 c = unpack2(acc1[j]);
        pbase[(size_t)(2 * j) * HWDIM + n1]     = c.x;
        pbase[(size_t)(2 * j + 1) * HWDIM + n1] = c.y;
    }
    d_psum[((size_t)b * MSPLIT + sp) * HWDIM + n0] = sum0;
    d_psum[((size_t)b * MSPLIT + sp) * HWDIM + n1] = sum1;
}

// ---------------------------------------------------------------------------
// Kernel C: combine partials, normalize, w_o GEMV, gamma * o + x.
// grid (16, 16), 256 threads. One thread per query. Memory-bound (~66MB).
// ---------------------------------------------------------------------------
__global__ __launch_bounds__(256) void combine_kernel(
    const float* __restrict__ x,
    const float* __restrict__ wo,
    const float* __restrict__ gamma,
    float* __restrict__ out)
{
    __shared__ u64 s_wo2[CDIM * 16];   // pairs over k: {wo[c][2j], wo[c][2j+1]}
    int tid = threadIdx.x;
    for (int i = tid; i < CDIM * 16; i += 256) {
        int c = i >> 4, j = i & 15;
        s_wo2[i] = pack2(wo[c * CG + 2 * j], wo[c * CG + 2 * j + 1]);
    }
    __syncthreads();

    int b = blockIdx.y;
    int n = blockIdx.x * 256 + tid;

    const float* p0 = &d_part[(((size_t)b * MSPLIT + 0) * CG) * HWDIM + n];
    const float* p1 = &d_part[(((size_t)b * MSPLIT + 1) * CG) * HWDIM + n];
    float s0 = d_psum[((size_t)b * MSPLIT + 0) * HWDIM + n];
    float s1 = d_psum[((size_t)b * MSPLIT + 1) * HWDIM + n];
    float inv = 1.0f / (s0 + s1);

    u64 o2[16];
#pragma unroll
    for (int j = 0; j < 16; j++) {
        float a0 = (p0[(size_t)(2 * j) * HWDIM]     + p1[(size_t)(2 * j) * HWDIM])     * inv;
        float a1 = (p0[(size_t)(2 * j + 1) * HWDIM] + p1[(size_t)(2 * j + 1) * HWDIM]) * inv;
        o2[j] = pack2(a0, a1);
    }

    float gm = *gamma;
    const float* xb = x   + (size_t)b * CDIM * HWDIM + n;
    float*       ob = out + (size_t)b * CDIM * HWDIM + n;
#pragma unroll
    for (int c = 0; c < CDIM; c++) {
        u64 v2 = 0ull;
#pragma unroll
        for (int j = 0; j < 16; j++) v2 = ffma2(s_wo2[c * 16 + j], o2[j], v2);
        float2 v = unpack2(v2);
        ob[(size_t)c * HWDIM] = fmaf(gm, v.x + v.y, xb[(size_t)c * HWDIM]);
    }
}

// ---------------------------------------------------------------------------
extern "C" void kernel_launch(void* const* d_in, const int* in_sizes, int n_in,
                              void* d_out, int out_size)
{
    const float* x  = (const float*)d_in[0];
    const float* wt = (const float*)d_in[1];
    const float* wp = (const float*)d_in[2];
    const float* wg = (const float*)d_in[3];
    const float* wo = (const float*)d_in[4];
    const float* gm = (const float*)d_in[5];
    float* out = (float*)d_out;

    proj_kernel<<<dim3(32, BATCH), 128>>>(x, wt, wp, wg);

    int smem_bytes = (MHALF * 4 + MHALF * 16) * (int)sizeof(u64);   // 81920
    cudaFuncSetAttribute(attn_kernel, cudaFuncAttributeMaxDynamicSharedMemorySize,
                         smem_bytes);
    attn_kernel<<<dim3(HWDIM / 512, MSPLIT, BATCH), 256, smem_bytes>>>();

    combine_kernel<<<dim3(HWDIM / 256, BATCH), 256>>>(x, wo, gm, out);
}